// round 2
// baseline (speedup 1.0000x reference)
#include <cuda_runtime.h>
#include <cstdint>
#include <cstddef>

#define NPT   4096
#define BBATCH 4
#define NPTS  (BBATCH*NPT)
#define KNB   20

// ------------------------- device scratch -------------------------
__device__ float g_pd[(size_t)BBATCH*NPT*NPT];   // 268 MB pairwise
__device__ int   g_idx[NPTS*KNB];
__device__ float g_pts[NPTS*3];
__device__ float g_p[NPTS*3];
__device__ float g_sq[NPTS];
__device__ float g_aA[NPTS*64];
__device__ float g_aB[NPTS*64];
__device__ float g_t[(size_t)NPTS*128];
__device__ float g_cat192[(size_t)NPTS*192];     // x1|x2|x3
__device__ float g_c2[(size_t)NPTS*512];
__device__ float g_c3[(size_t)NPTS*256];
__device__ float g_tvec[BBATCH*1024];
__device__ float g_gvec[BBATCH*1024];
__device__ float g_fc1[BBATCH*512];
__device__ float g_fc2[BBATCH*256];
__device__ float g_xf[BBATCH*9];
__device__ float g_gterm[BBATCH*512];

// ------------------------- small kernels -------------------------
__global__ void k_zero() {
    int t = blockIdx.x*blockDim.x + threadIdx.x;
    if (t < BBATCH*1024) { g_tvec[t] = 0.f; g_gvec[t] = 0.f; }
}

__global__ void k_pts_sq(const float* __restrict__ x) {
    int i = blockIdx.x*blockDim.x + threadIdx.x;
    if (i >= NPTS) return;
    float a = x[i*6+0], b = x[i*6+1], c = x[i*6+2];
    g_pts[i*3+0] = a; g_pts[i*3+1] = b; g_pts[i*3+2] = c;
    g_sq[i] = a*a + b*b + c*c;
}

__global__ void k_transform() {
    int n = blockIdx.x*blockDim.x + threadIdx.x;
    if (n >= NPTS) return;
    int b = n >> 12;
    float x = g_pts[n*3], y = g_pts[n*3+1], z = g_pts[n*3+2];
    const float* f = g_xf + b*9;
    float p0 = x*f[0] + y*f[3] + z*f[6];
    float p1 = x*f[1] + y*f[4] + z*f[7];
    float p2 = x*f[2] + y*f[5] + z*f[8];
    g_p[n*3+0] = p0; g_p[n*3+1] = p1; g_p[n*3+2] = p2;
    g_sq[n] = p0*p0 + p1*p1 + p2*p2;
}

__global__ void k_sq64(const float* __restrict__ src, int ld) {
    int gt = blockIdx.x*blockDim.x + threadIdx.x;
    int w = gt >> 5, lane = gt & 31;
    if (w >= NPTS) return;
    const float* r = src + (size_t)w*ld;
    float s = r[lane]*r[lane] + r[lane+32]*r[lane+32];
    #pragma unroll
    for (int off = 16; off; off >>= 1) s += __shfl_down_sync(0xffffffffu, s, off);
    if (lane == 0) g_sq[w] = s;
}

// ------------------------- pairwise distances -------------------------
__global__ void k_pairwise3(const float* __restrict__ P) {
    size_t t = (size_t)blockIdx.x*blockDim.x + threadIdx.x;
    if (t >= (size_t)BBATCH*NPT*NPT) return;
    int j = (int)(t & (NPT-1));
    size_t bi = t >> 12;
    int i = (int)(bi & (NPT-1));
    int b = (int)(bi >> 12);
    const float* pi = P + ((size_t)b*NPT + i)*3;
    const float* pj = P + ((size_t)b*NPT + j)*3;
    float dot = pi[0]*pj[0] + pi[1]*pj[1] + pi[2]*pj[2];
    g_pd[t] = 2.f*dot - g_sq[(size_t)b*NPT+i] - g_sq[(size_t)b*NPT+j];
}

__global__ void __launch_bounds__(256) k_pairwise64(const float* __restrict__ X, int ld) {
    __shared__ float Xi[16][68];
    __shared__ float Xj[16][68];
    int b = blockIdx.z;
    int i0 = blockIdx.y*64, j0 = blockIdx.x*64;
    const float* Xb = X + (size_t)b*NPT*ld;
    int t = threadIdx.x, tx = t & 15, ty = t >> 4;
    int lr = t >> 2, lc = (t & 3)*4;
    float acc[4][4] = {};
    for (int kk = 0; kk < 64; kk += 16) {
        float4 av = *(const float4*)(Xb + (size_t)(i0+lr)*ld + kk + lc);
        float4 cv = *(const float4*)(Xb + (size_t)(j0+lr)*ld + kk + lc);
        Xi[lc+0][lr] = av.x; Xi[lc+1][lr] = av.y; Xi[lc+2][lr] = av.z; Xi[lc+3][lr] = av.w;
        Xj[lc+0][lr] = cv.x; Xj[lc+1][lr] = cv.y; Xj[lc+2][lr] = cv.z; Xj[lc+3][lr] = cv.w;
        __syncthreads();
        #pragma unroll
        for (int k = 0; k < 16; k++) {
            float ar[4], cr[4];
            #pragma unroll
            for (int r = 0; r < 4; r++) ar[r] = Xi[k][ty*4+r];
            #pragma unroll
            for (int s = 0; s < 4; s++) cr[s] = Xj[k][tx*4+s];
            #pragma unroll
            for (int r = 0; r < 4; r++)
                #pragma unroll
                for (int s = 0; s < 4; s++) acc[r][s] += ar[r]*cr[s];
        }
        __syncthreads();
    }
    float si[4], sj[4];
    #pragma unroll
    for (int r = 0; r < 4; r++) si[r] = g_sq[(size_t)b*NPT + i0 + ty*4 + r];
    #pragma unroll
    for (int s = 0; s < 4; s++) sj[s] = g_sq[(size_t)b*NPT + j0 + tx*4 + s];
    #pragma unroll
    for (int r = 0; r < 4; r++) {
        float4 v;
        v.x = 2.f*acc[r][0] - si[r] - sj[0];
        v.y = 2.f*acc[r][1] - si[r] - sj[1];
        v.z = 2.f*acc[r][2] - si[r] - sj[2];
        v.w = 2.f*acc[r][3] - si[r] - sj[3];
        *(float4*)(g_pd + ((size_t)b*NPT + i0 + ty*4 + r)*NPT + j0 + tx*4) = v;
    }
}

// ------------------------- top-K selection (K=20) -------------------------
__global__ void __launch_bounds__(128) k_topk() {
    __shared__ float sv[4][21*32];
    __shared__ int   si[4][21*32];
    int w = threadIdx.x >> 5, lane = threadIdx.x & 31;
    int row = blockIdx.x*4 + w;           // global point index
    int b = row >> 12, i = row & (NPT-1);
    const float* pd = g_pd + ((size_t)b*NPT + i)*NPT;
    float lv[20]; int li[20];
    #pragma unroll
    for (int q = 0; q < 20; q++) { lv[q] = -3.4e38f; li[q] = 0x7fffffff; }
    for (int t = 0; t < 128; t++) {
        int j = lane + (t << 5);
        float val = pd[j];
        if (val > lv[19]) {
            // branch-free downward insertion (ties keep earlier index)
            #pragma unroll
            for (int p = 19; p > 0; --p) {
                bool below = (lv[p] >= val);
                bool shift = (lv[p-1] < val);
                float nl = below ? lv[p] : (shift ? lv[p-1] : val);
                int   ni = below ? li[p] : (shift ? li[p-1] : j);
                lv[p] = nl; li[p] = ni;
            }
            if (lv[0] < val) { lv[0] = val; li[0] = j; }
        }
    }
    #pragma unroll
    for (int q = 0; q < 20; q++) { sv[w][q*32+lane] = lv[q]; si[w][q*32+lane] = li[q]; }
    sv[w][20*32+lane] = -3.4e38f; si[w][20*32+lane] = 0x7fffffff;  // sentinel
    __syncwarp();
    int ptr = 0;
    int* orow = g_idx + row*KNB;
    #pragma unroll
    for (int r = 0; r < 20; r++) {
        float v = sv[w][ptr*32+lane];
        int  id = si[w][ptr*32+lane];
        float bv = v; int bi = id;
        #pragma unroll
        for (int off = 16; off; off >>= 1) {
            float ov = __shfl_xor_sync(0xffffffffu, bv, off);
            int   oi = __shfl_xor_sync(0xffffffffu, bi, off);
            if (ov > bv || (ov == bv && oi < bi)) { bv = ov; bi = oi; }
        }
        if (lane == 0) orow[r] = (b << 12) + bi;   // store GLOBAL index
        if (id == bi) ptr++;
    }
}

// ------------------------- edge-conv prep: a[n], bnb[n] -------------------------
template<int C>
__global__ void k_prep_ab(const float* __restrict__ src, int ld,
                          const float* __restrict__ W, const float* __restrict__ bias) {
    __shared__ float Ws[2*C*64];
    for (int e = threadIdx.x; e < 2*C*64; e += blockDim.x) Ws[e] = W[e];
    __syncthreads();
    int t = blockIdx.x*blockDim.x + threadIdx.x;
    int d = t & 63, n = t >> 6;
    if (n >= NPTS) return;
    const float* xr = src + (size_t)n*ld;
    float a = bias[d], bb = 0.f;
    #pragma unroll
    for (int c = 0; c < C; c++) {
        float xv = xr[c];
        float wt = Ws[c*64+d], wb = Ws[(C+c)*64+d];
        a  += xv*(wt - wb);
        bb += xv*wb;
    }
    g_aA[(size_t)n*64+d] = a;
    g_aB[(size_t)n*64+d] = bb;
}

// ------------------------- fused edge conv2 + k-max -------------------------
// out[n,:] = max_k relu( relu(a[n]+bnb[idx[n,k]]) @ W2 + b2 )
template<int D2>
__global__ void __launch_bounds__(256) k_edge_fused(const float* __restrict__ W2,
                                                    const float* __restrict__ b2,
                                                    float* __restrict__ out, int ldo) {
    __shared__ float Ws[64*D2];
    __shared__ float bs[D2];
    for (int e = threadIdx.x; e < 64*D2; e += 256) Ws[e] = W2[e];
    for (int e = threadIdx.x; e < D2; e += 256) bs[e] = b2[e];
    __syncthreads();
    const int NQ = D2/32;
    int w = threadIdx.x >> 5, lane = threadIdx.x & 31;
    int n = blockIdx.x*8 + w;
    float a0 = g_aA[(size_t)n*64 + lane];
    float a1 = g_aA[(size_t)n*64 + 32 + lane];
    float mx[NQ];
    #pragma unroll
    for (int q = 0; q < NQ; q++) mx[q] = 0.f;
    const int* ir = g_idx + n*KNB;
    for (int kk = 0; kk < KNB; kk += 4) {
        float h0[4], h1[4];
        #pragma unroll
        for (int e = 0; e < 4; e++) {
            int j = ir[kk+e];
            h0[e] = fmaxf(a0 + g_aB[(size_t)j*64 + lane], 0.f);
            h1[e] = fmaxf(a1 + g_aB[(size_t)j*64 + 32 + lane], 0.f);
        }
        float z[4][NQ];
        #pragma unroll
        for (int e = 0; e < 4; e++)
            #pragma unroll
            for (int q = 0; q < NQ; q++) z[e][q] = bs[lane + 32*q];
        #pragma unroll
        for (int c = 0; c < 32; c++) {
            float wv[NQ];
            #pragma unroll
            for (int q = 0; q < NQ; q++) wv[q] = Ws[c*D2 + lane + 32*q];
            #pragma unroll
            for (int e = 0; e < 4; e++) {
                float hc = __shfl_sync(0xffffffffu, h0[e], c);
                #pragma unroll
                for (int q = 0; q < NQ; q++) z[e][q] += hc*wv[q];
            }
        }
        #pragma unroll
        for (int c = 0; c < 32; c++) {
            float wv[NQ];
            #pragma unroll
            for (int q = 0; q < NQ; q++) wv[q] = Ws[(32+c)*D2 + lane + 32*q];
            #pragma unroll
            for (int e = 0; e < 4; e++) {
                float hc = __shfl_sync(0xffffffffu, h1[e], c);
                #pragma unroll
                for (int q = 0; q < NQ; q++) z[e][q] += hc*wv[q];
            }
        }
        #pragma unroll
        for (int e = 0; e < 4; e++)
            #pragma unroll
            for (int q = 0; q < NQ; q++) mx[q] = fmaxf(mx[q], z[e][q]);
    }
    #pragma unroll
    for (int q = 0; q < NQ; q++) out[(size_t)n*ldo + lane + 32*q] = mx[q];
}

// e3: out[n,d] = max_k relu(a[n,d] + bnb[idx[n,k],d])
__global__ void k_edge_e3(float* __restrict__ out, int ldo) {
    int t = blockIdx.x*blockDim.x + threadIdx.x;
    int d = t & 63, n = t >> 6;
    if (n >= NPTS) return;
    float a = g_aA[(size_t)n*64+d];
    const int* ir = g_idx + n*KNB;
    float m = 0.f;
    #pragma unroll
    for (int k = 0; k < KNB; k++) m = fmaxf(m, a + g_aB[(size_t)ir[k]*64 + d]);
    out[(size_t)n*ldo + d] = m;
}

// ------------------------- generic fp32 GEMM -------------------------
// M=16384 fixed by grid.y*64; Kd%16==0, Nd%64==0.
// AMAX: per-batch (4096 rows) max-reduce via atomicMax; out is [4][Nd], pre-zeroed.
template<bool RELU, bool AMAX>
__global__ void __launch_bounds__(256) k_gemm(const float* __restrict__ A, int lda,
                                              const float* __restrict__ W, int ldw,
                                              const float* __restrict__ bias,
                                              const float* __restrict__ rowadd,
                                              float* __restrict__ out,
                                              int Kd, int Nd) {
    __shared__ float As[16][68];
    __shared__ float Ws[16][68];
    int m0 = blockIdx.y*64, n0 = blockIdx.x*64;
    int t = threadIdx.x, tx = t & 15, ty = t >> 4;
    int la_m = t >> 2, la_k = (t & 3)*4;
    int lw_k = t >> 4, lw_n = (t & 15)*4;
    float acc[4][4] = {};
    for (int kk = 0; kk < Kd; kk += 16) {
        float4 av = *(const float4*)(A + (size_t)(m0+la_m)*lda + kk + la_k);
        float4 wv = *(const float4*)(W + (size_t)(kk+lw_k)*ldw + n0 + lw_n);
        As[la_k+0][la_m] = av.x; As[la_k+1][la_m] = av.y;
        As[la_k+2][la_m] = av.z; As[la_k+3][la_m] = av.w;
        *(float4*)&Ws[lw_k][lw_n] = wv;
        __syncthreads();
        #pragma unroll
        for (int k = 0; k < 16; k++) {
            float ar[4], wr[4];
            #pragma unroll
            for (int r = 0; r < 4; r++) ar[r] = As[k][ty*4+r];
            #pragma unroll
            for (int s = 0; s < 4; s++) wr[s] = Ws[k][tx*4+s];
            #pragma unroll
            for (int r = 0; r < 4; r++)
                #pragma unroll
                for (int s = 0; s < 4; s++) acc[r][s] += ar[r]*wr[s];
        }
        __syncthreads();
    }
    int b = m0 >> 12;
    if (!AMAX) {
        #pragma unroll
        for (int r = 0; r < 4; r++) {
            float vv[4];
            #pragma unroll
            for (int s = 0; s < 4; s++) {
                int n = n0 + tx*4 + s;
                float x = acc[r][s];
                if (bias)   x += bias[n];
                if (rowadd) x += rowadd[b*Nd + n];
                if (RELU)   x = fmaxf(x, 0.f);
                vv[s] = x;
            }
            *(float4*)(out + (size_t)(m0+ty*4+r)*Nd + n0 + tx*4) =
                make_float4(vv[0], vv[1], vv[2], vv[3]);
        }
    } else {
        float cm[4];
        #pragma unroll
        for (int s = 0; s < 4; s++) cm[s] = 0.f;
        #pragma unroll
        for (int r = 0; r < 4; r++)
            #pragma unroll
            for (int s = 0; s < 4; s++) {
                float x = acc[r][s];
                if (bias) x += bias[n0+tx*4+s];
                x = fmaxf(x, 0.f);
                cm[s] = fmaxf(cm[s], x);
            }
        #pragma unroll
        for (int s = 0; s < 4; s++) As[ty][tx*4+s] = cm[s];
        __syncthreads();
        #pragma unroll
        for (int st = 8; st >= 1; st >>= 1) {
            if (ty < st) {
                #pragma unroll
                for (int s = 0; s < 4; s++)
                    As[ty][tx*4+s] = fmaxf(As[ty][tx*4+s], As[ty+st][tx*4+s]);
            }
            __syncthreads();
        }
        if (ty == 0) {
            #pragma unroll
            for (int s = 0; s < 4; s++)
                atomicMax((int*)out + (size_t)b*Nd + n0 + tx*4 + s,
                          __float_as_int(As[0][tx*4+s]));
        }
    }
}

// ------------------------- small FC (M=4) -------------------------
__global__ void k_fc(const float* __restrict__ A, const float* __restrict__ W, int ldw,
                     const float* __restrict__ bias, float* __restrict__ out,
                     int Kd, int Nd, int relu) {
    int t = blockIdx.x*blockDim.x + threadIdx.x;
    if (t >= BBATCH*Nd) return;
    int b = t / Nd, d = t - b*Nd;
    const float* ar = A + (size_t)b*Kd;
    float s0 = 0.f, s1 = 0.f, s2 = 0.f, s3 = 0.f;
    for (int c = 0; c < Kd; c += 4) {
        s0 += ar[c+0]*W[(size_t)(c+0)*ldw + d];
        s1 += ar[c+1]*W[(size_t)(c+1)*ldw + d];
        s2 += ar[c+2]*W[(size_t)(c+2)*ldw + d];
        s3 += ar[c+3]*W[(size_t)(c+3)*ldw + d];
    }
    float acc = bias[d] + (s0+s1) + (s2+s3);
    if (relu) acc = fmaxf(acc, 0.f);
    out[(size_t)b*Nd + d] = acc;
}

// ------------------------- final 256->2 -------------------------
__global__ void k_c4(const float* __restrict__ W, const float* __restrict__ bias,
                     float* __restrict__ out) {
    int gt = blockIdx.x*blockDim.x + threadIdx.x;
    int w = gt >> 5, lane = gt & 31;
    if (w >= NPTS) return;
    const float* a = g_c3 + (size_t)w*256;
    float s0 = 0.f, s1 = 0.f;
    #pragma unroll
    for (int t = 0; t < 8; t++) {
        int c = lane + 32*t;
        float v = a[c];
        s0 += v*W[c*2+0];
        s1 += v*W[c*2+1];
    }
    #pragma unroll
    for (int off = 16; off; off >>= 1) {
        s0 += __shfl_down_sync(0xffffffffu, s0, off);
        s1 += __shfl_down_sync(0xffffffffu, s1, off);
    }
    if (lane == 0) { out[w*2+0] = s0 + bias[0]; out[w*2+1] = s1 + bias[1]; }
}

// ------------------------- host orchestration -------------------------
static float* symaddr(const void* sym) {
    void* p = nullptr;
    cudaGetSymbolAddress(&p, sym);
    return (float*)p;
}

extern "C" void kernel_launch(void* const* d_in, const int* in_sizes, int n_in,
                              void* d_out, int out_size) {
    const float* x    = (const float*)d_in[0];
    const float* tw1  = (const float*)d_in[1];
    const float* tb1  = (const float*)d_in[2];
    const float* tw2  = (const float*)d_in[3];
    const float* tb2  = (const float*)d_in[4];
    const float* tw3  = (const float*)d_in[5];
    const float* tb3  = (const float*)d_in[6];
    const float* tfw1 = (const float*)d_in[7];
    const float* tfb1 = (const float*)d_in[8];
    const float* tfw2 = (const float*)d_in[9];
    const float* tfb2 = (const float*)d_in[10];
    const float* txw  = (const float*)d_in[11];
    const float* txb  = (const float*)d_in[12];
    const float* e1w1 = (const float*)d_in[13];
    const float* e1b1 = (const float*)d_in[14];
    const float* e1w2 = (const float*)d_in[15];
    const float* e1b2 = (const float*)d_in[16];
    const float* e2w1 = (const float*)d_in[17];
    const float* e2b1 = (const float*)d_in[18];
    const float* e2w2 = (const float*)d_in[19];
    const float* e2b2 = (const float*)d_in[20];
    const float* e3w1 = (const float*)d_in[21];
    const float* e3b1 = (const float*)d_in[22];
    const float* c1w  = (const float*)d_in[23];
    const float* c1b  = (const float*)d_in[24];
    const float* c2w  = (const float*)d_in[25];
    const float* c2b  = (const float*)d_in[26];
    const float* c3w  = (const float*)d_in[27];
    const float* c3b  = (const float*)d_in[28];
    const float* c4w  = (const float*)d_in[29];
    const float* c4b  = (const float*)d_in[30];
    float* out = (float*)d_out;

    float* p_pts   = symaddr(g_pts);
    float* p_p     = symaddr(g_p);
    float* p_t     = symaddr(g_t);
    float* p_cat   = symaddr(g_cat192);
    float* p_c2    = symaddr(g_c2);
    float* p_c3    = symaddr(g_c3);
    float* p_tvec  = symaddr(g_tvec);
    float* p_gvec  = symaddr(g_gvec);
    float* p_fc1   = symaddr(g_fc1);
    float* p_fc2   = symaddr(g_fc2);
    float* p_xf    = symaddr(g_xf);
    float* p_gterm = symaddr(g_gterm);

    const size_t PD_ELEMS = (size_t)BBATCH*NPT*NPT;
    dim3 pwgrid(NPT/64, NPT/64, BBATCH);

    k_zero<<<(BBATCH*1024 + 255)/256, 256>>>();
    k_pts_sq<<<NPTS/256, 256>>>(x);

    // ---- knn(pts) + tnet ----
    k_pairwise3<<<(unsigned)(PD_ELEMS/256), 256>>>(p_pts);
    k_topk<<<NPTS/4, 128>>>();
    k_prep_ab<3><<<NPTS*64/256, 256>>>(p_pts, 3, tw1, tb1);
    k_edge_fused<128><<<NPTS/8, 256>>>(tw2, tb2, p_t, 128);
    k_gemm<true, true><<<dim3(1024/64, NPTS/64), 256>>>(p_t, 128, tw3, 1024, tb3, nullptr, p_tvec, 128, 1024);
    k_fc<<<(BBATCH*512 + 127)/128, 128>>>(p_tvec, tfw1, 512, tfb1, p_fc1, 1024, 512, 1);
    k_fc<<<(BBATCH*256 + 127)/128, 128>>>(p_fc1, tfw2, 256, tfb2, p_fc2, 512, 256, 1);
    k_fc<<<1, 128>>>(p_fc2, txw, 9, txb, p_xf, 256, 9, 0);
    k_transform<<<NPTS/256, 256>>>();

    // ---- knn(p) + e1 -> x1 ----
    k_pairwise3<<<(unsigned)(PD_ELEMS/256), 256>>>(p_p);
    k_topk<<<NPTS/4, 128>>>();
    k_prep_ab<3><<<NPTS*64/256, 256>>>(p_p, 3, e1w1, e1b1);
    k_edge_fused<64><<<NPTS/8, 256>>>(e1w2, e1b2, p_cat + 0, 192);

    // ---- knn(x1) + e2 -> x2 ----
    k_sq64<<<NPTS*32/256, 256>>>(p_cat + 0, 192);
    k_pairwise64<<<pwgrid, 256>>>(p_cat + 0, 192);
    k_topk<<<NPTS/4, 128>>>();
    k_prep_ab<64><<<NPTS*64/256, 256>>>(p_cat + 0, 192, e2w1, e2b1);
    k_edge_fused<64><<<NPTS/8, 256>>>(e2w2, e2b2, p_cat + 64, 192);

    // ---- knn(x2) + e3 -> x3 ----
    k_sq64<<<NPTS*32/256, 256>>>(p_cat + 64, 192);
    k_pairwise64<<<pwgrid, 256>>>(p_cat + 64, 192);
    k_topk<<<NPTS/4, 128>>>();
    k_prep_ab<64><<<NPTS*64/256, 256>>>(p_cat + 64, 192, e3w1, e3b1);
    k_edge_e3<<<NPTS*64/256, 256>>>(p_cat + 128, 192);

    // ---- classifier ----
    k_gemm<true, true><<<dim3(1024/64, NPTS/64), 256>>>(p_cat, 192, c1w, 1024, c1b, nullptr, p_gvec, 192, 1024);
    k_fc<<<(BBATCH*512 + 127)/128, 128>>>(p_gvec, c2w, 512, c2b, p_gterm, 1024, 512, 0);
    k_gemm<true, false><<<dim3(512/64, NPTS/64), 256>>>(p_cat, 192, c2w + (size_t)1024*512, 512, nullptr, p_gterm, p_c2, 192, 512);
    k_gemm<true, false><<<dim3(256/64, NPTS/64), 256>>>(p_c2, 512, c3w, 256, c3b, nullptr, p_c3, 512, 256);
    k_c4<<<NPTS*32/256, 256>>>(c4w, c4b, out);
}